// round 1
// baseline (speedup 1.0000x reference)
#include <cuda_runtime.h>
#include <math.h>

// LSTM cell: x = concat(hidden, inputs)  [4096 x 2048]
// pre_g = x @ W_g + b_g   for g in {f, i, c, o},  W_g: [2048 x 1024] row-major
// new_cell = sigmoid(pre_f)*cell + sigmoid(pre_i)*tanh(pre_c)
// new_hidden = sigmoid(pre_o)*tanh(new_cell)
// Output layout: d_out[0 : B*U] = new_hidden, d_out[B*U : 2*B*U] = new_cell

#define BATCH 4096
#define UNITS 1024
#define INDIM 1024
#define KDIM  (UNITS + INDIM)   // 2048

#define BM 64
#define BN 64
#define BK 16
#define TM 4
#define TN 4
// threads = (BM/TM) * (BN/TN) = 16*16 = 256

__device__ __forceinline__ float sigmoidf_(float x) {
    return 1.0f / (1.0f + expf(-x));
}

__global__ __launch_bounds__(256)
void lstm_fused_kernel(
    const float* __restrict__ inp,   // [B, 1024]
    const float* __restrict__ hid,   // [B, 1024]
    const float* __restrict__ cell,  // [B, 1024]
    const float* __restrict__ Wf, const float* __restrict__ bf,
    const float* __restrict__ Wi, const float* __restrict__ bi,
    const float* __restrict__ Wc, const float* __restrict__ bc,
    const float* __restrict__ Wo, const float* __restrict__ bo,
    float* __restrict__ out_h,
    float* __restrict__ out_c)
{
    __shared__ float As[BK][BM];        // x tile, transposed: As[k][m]
    __shared__ float Bs[4][BK][BN];     // 4 gate weight tiles: Bs[g][k][n]

    const int tid = threadIdx.x;
    const int tx  = tid & 15;   // n direction (0..15)
    const int ty  = tid >> 4;   // m direction (0..15)

    const int brow0 = blockIdx.y * BM;  // batch offset
    const int bcol0 = blockIdx.x * BN;  // unit offset

    // A-tile load mapping: 256 threads * 4 floats = 1024 = 64x16
    const int a_row = tid >> 2;          // 0..63
    const int a_kk  = (tid & 3) << 2;    // 0,4,8,12

    // B-tile load mapping: 256 threads * 4 floats = 1024 = 16x64 per gate
    const int b_k  = tid >> 4;           // 0..15
    const int b_n4 = (tid & 15) << 2;    // 0..60

    const float* Wg[4] = {Wf, Wi, Wc, Wo};

    float acc[4][TM][TN];
    #pragma unroll
    for (int g = 0; g < 4; g++)
        #pragma unroll
        for (int i = 0; i < TM; i++)
            #pragma unroll
            for (int j = 0; j < TN; j++)
                acc[g][i][j] = 0.0f;

    for (int k0 = 0; k0 < KDIM; k0 += BK) {
        // ---- load x tile (concat handled per K-tile; boundary 1024 is BK-aligned)
        const float* xsrc = (k0 < UNITS) ? hid : inp;
        const int kloc = (k0 < UNITS) ? k0 : (k0 - UNITS);
        float4 av = *reinterpret_cast<const float4*>(
            &xsrc[(size_t)(brow0 + a_row) * 1024 + kloc + a_kk]);
        As[a_kk + 0][a_row] = av.x;
        As[a_kk + 1][a_row] = av.y;
        As[a_kk + 2][a_row] = av.z;
        As[a_kk + 3][a_row] = av.w;

        // ---- load 4 weight tiles
        #pragma unroll
        for (int g = 0; g < 4; g++) {
            float4 bv = *reinterpret_cast<const float4*>(
                &Wg[g][(size_t)(k0 + b_k) * 1024 + bcol0 + b_n4]);
            *reinterpret_cast<float4*>(&Bs[g][b_k][b_n4]) = bv;
        }
        __syncthreads();

        // ---- compute
        #pragma unroll
        for (int k = 0; k < BK; k++) {
            float4 a4 = *reinterpret_cast<const float4*>(&As[k][ty << 2]);
            float a_[4] = {a4.x, a4.y, a4.z, a4.w};
            #pragma unroll
            for (int g = 0; g < 4; g++) {
                float4 b4 = *reinterpret_cast<const float4*>(&Bs[g][k][tx << 2]);
                float b_[4] = {b4.x, b4.y, b4.z, b4.w};
                #pragma unroll
                for (int i = 0; i < TM; i++)
                    #pragma unroll
                    for (int j = 0; j < TN; j++)
                        acc[g][i][j] = fmaf(a_[i], b_[j], acc[g][i][j]);
            }
        }
        __syncthreads();
    }

    // ---- epilogue: gates + cell update, write both outputs
    #pragma unroll
    for (int i = 0; i < TM; i++) {
        const int row = brow0 + (ty << 2) + i;
        #pragma unroll
        for (int j = 0; j < TN; j++) {
            const int col = bcol0 + (tx << 2) + j;
            const float pf = acc[0][i][j] + bf[col];
            const float pi = acc[1][i][j] + bi[col];
            const float pc = acc[2][i][j] + bc[col];
            const float po = acc[3][i][j] + bo[col];

            const float f  = sigmoidf_(pf);
            const float ig = sigmoidf_(pi);
            const float cc = tanhf(pc);
            const float o  = sigmoidf_(po);

            const float cprev = cell[(size_t)row * UNITS + col];
            const float nc = f * cprev + ig * cc;
            const float nh = o * tanhf(nc);

            out_h[(size_t)row * UNITS + col] = nh;
            out_c[(size_t)row * UNITS + col] = nc;
        }
    }
}

extern "C" void kernel_launch(void* const* d_in, const int* in_sizes, int n_in,
                              void* d_out, int out_size) {
    const float* inp  = (const float*)d_in[0];
    const float* hid  = (const float*)d_in[1];
    const float* cell = (const float*)d_in[2];
    const float* Wf   = (const float*)d_in[3];
    const float* bf   = (const float*)d_in[4];
    const float* Wi   = (const float*)d_in[5];
    const float* bi   = (const float*)d_in[6];
    const float* Wc   = (const float*)d_in[7];
    const float* bc   = (const float*)d_in[8];
    const float* Wo   = (const float*)d_in[9];
    const float* bo   = (const float*)d_in[10];

    float* out_h = (float*)d_out;
    float* out_c = out_h + (size_t)BATCH * UNITS;

    dim3 grid(UNITS / BN, BATCH / BM);   // (16, 64)
    dim3 block(256);
    lstm_fused_kernel<<<grid, block>>>(inp, hid, cell,
                                       Wf, bf, Wi, bi, Wc, bc, Wo, bo,
                                       out_h, out_c);
}

// round 3
// speedup vs baseline: 2.0391x; 2.0391x over previous
#include <cuda_runtime.h>
#include <cuda_bf16.h>
#include <cstdint>
#include <math.h>

// LSTM cell via warp-level mma.sync bf16 (HMMA) with 2-term bf16 split.
// P[4096 x 4096] = X[4096 x 2048] @ W_all[2048 x 4096]  (4 gates along N)
// computed as Ah*Bh + Ah*Bl + Al*Bh (fp32 accum), then gate epilogue.

#define BATCH 4096
#define UNITS 1024
#define KDIM  2048
#define NTOT  4096          // 4 gates * 1024

#define BM 128
#define BN 128
#define BK 32
#define NSTAGE (KDIM / BK)  // 64

// SMEM layout per stage: 4 tiles [128 rows][32 bf16], row stride 40 elems (80B)
#define ROWS_PER_TILE 128
#define ROW_STRIDE_EL 40
#define ROW_STRIDE_B  80
#define TILE_B (ROWS_PER_TILE * ROW_STRIDE_B)   // 10240
#define OFF_AH 0
#define OFF_AL TILE_B
#define OFF_BH (2 * TILE_B)
#define OFF_BL (3 * TILE_B)
#define STAGE_B (4 * TILE_B)                    // 40960
#define SMEM_TOTAL (2 * STAGE_B)                // 81920

// ---------------- device scratch ----------------
__device__ __nv_bfloat16 g_Ah[(size_t)BATCH * KDIM];
__device__ __nv_bfloat16 g_Al[(size_t)BATCH * KDIM];
__device__ __nv_bfloat16 g_Bh[(size_t)NTOT * KDIM];   // N-major: row = gate*1024+n
__device__ __nv_bfloat16 g_Bl[(size_t)NTOT * KDIM];
__device__ float g_P[(size_t)BATCH * NTOT];           // pre-activations

// ---------------- helpers ----------------
__device__ __forceinline__ uint32_t smem_u32(const void* p) {
    uint32_t a;
    asm("{ .reg .u64 t; cvta.to.shared.u64 t, %1; cvt.u32.u64 %0, t; }" : "=r"(a) : "l"(p));
    return a;
}
__device__ __forceinline__ void cp16(uint32_t dst, const void* src) {
    asm volatile("cp.async.cg.shared.global [%0], [%1], 16;" :: "r"(dst), "l"(src));
}
#define CP_COMMIT() asm volatile("cp.async.commit_group;" ::: "memory")
#define CP_WAIT(n)  asm volatile("cp.async.wait_group %0;" :: "n"(n) : "memory")

__device__ __forceinline__ void mma_bf16(float* c, const uint32_t* a, const uint32_t* b) {
    asm volatile(
        "mma.sync.aligned.m16n8k16.row.col.f32.bf16.bf16.f32 "
        "{%0,%1,%2,%3}, {%4,%5,%6,%7}, {%8,%9}, {%0,%1,%2,%3};"
        : "+f"(c[0]), "+f"(c[1]), "+f"(c[2]), "+f"(c[3])
        : "r"(a[0]), "r"(a[1]), "r"(a[2]), "r"(a[3]), "r"(b[0]), "r"(b[1]));
}

__device__ __forceinline__ float sig_(float x) {
    x = fminf(fmaxf(x, -30.f), 30.f);
    return __fdividef(1.f, 1.f + __expf(-x));
}
__device__ __forceinline__ float tanh_(float x) {
    x = fminf(fmaxf(x, -15.f), 15.f);
    float e = __expf(2.f * x);
    return __fdividef(e - 1.f, e + 1.f);
}

// ---------------- split precompute ----------------
__global__ __launch_bounds__(256) void split_a_kernel(
    const float* __restrict__ hid, const float* __restrict__ inp)
{
    int i4 = blockIdx.x * 256 + threadIdx.x;   // float4 index over [4096][512]
    int row = i4 >> 9;
    int c4  = i4 & 511;
    const float4 v = (c4 < 256)
        ? *(const float4*)&hid[(size_t)row * 1024 + c4 * 4]
        : *(const float4*)&inp[(size_t)row * 1024 + (c4 - 256) * 4];
    __nv_bfloat16 h[4], l[4];
    const float vv[4] = {v.x, v.y, v.z, v.w};
    #pragma unroll
    for (int j = 0; j < 4; j++) {
        h[j] = __float2bfloat16_rn(vv[j]);
        l[j] = __float2bfloat16_rn(vv[j] - __bfloat162float(h[j]));
    }
    size_t o = (size_t)row * KDIM + c4 * 4;
    *(uint2*)&g_Ah[o] = *(uint2*)h;
    *(uint2*)&g_Al[o] = *(uint2*)l;
}

__global__ __launch_bounds__(256) void split_b_kernel(
    const float* __restrict__ Wf, const float* __restrict__ Wi,
    const float* __restrict__ Wc, const float* __restrict__ Wo)
{
    __shared__ float tile[32][33];
    const int g = blockIdx.z;
    const float* W = (g == 0) ? Wf : (g == 1) ? Wi : (g == 2) ? Wc : Wo;
    const int n0 = blockIdx.x * 32;
    const int k0 = blockIdx.y * 32;
    const int tx = threadIdx.x & 31;
    const int ty = threadIdx.x >> 5;   // 0..7
    #pragma unroll
    for (int j = 0; j < 4; j++)
        tile[ty + 8 * j][tx] = W[(size_t)(k0 + ty + 8 * j) * UNITS + n0 + tx];
    __syncthreads();
    // write transposed: output row = gate*1024 + n, k contiguous; 4 bf16 per thread
    const int n_l = threadIdx.x >> 3;        // 0..31
    const int kq  = (threadIdx.x & 7) * 4;   // 0..28
    __nv_bfloat16 h[4], l[4];
    #pragma unroll
    for (int j = 0; j < 4; j++) {
        float v = tile[kq + j][n_l];
        h[j] = __float2bfloat16_rn(v);
        l[j] = __float2bfloat16_rn(v - __bfloat162float(h[j]));
    }
    size_t o = ((size_t)g * UNITS + n0 + n_l) * KDIM + k0 + kq;
    *(uint2*)&g_Bh[o] = *(uint2*)h;
    *(uint2*)&g_Bl[o] = *(uint2*)l;
}

// ---------------- main GEMM (HMMA bf16, 3 products) ----------------
__global__ __launch_bounds__(256, 1) void gemm_kernel()
{
    extern __shared__ char smem[];
    const uint32_t sb = smem_u32(smem);
    const int tid  = threadIdx.x;
    const int wid  = tid >> 5;
    const int lane = tid & 31;
    const int warp_m = wid & 1;        // 0..1 -> 64 rows each
    const int warp_n = wid >> 1;       // 0..3 -> 32 cols each
    const int m0 = blockIdx.y * BM;
    const int n0 = blockIdx.x * BN;

    // global->smem load mapping: per array, 512 x 16B chunks; 2 per thread
    const int j0 = tid, j1 = tid + 256;
    const int r0 = j0 >> 2, c0 = j0 & 3;
    const int r1 = j1 >> 2, c1 = j1 & 3;

    auto issue_stage = [&](int s) {
        const int k0 = s * BK;
        const uint32_t base = sb + (s & 1) * STAGE_B;
        // A tiles (rows = batch)
        cp16(base + OFF_AH + r0 * ROW_STRIDE_B + c0 * 16, &g_Ah[(size_t)(m0 + r0) * KDIM + k0 + c0 * 8]);
        cp16(base + OFF_AH + r1 * ROW_STRIDE_B + c1 * 16, &g_Ah[(size_t)(m0 + r1) * KDIM + k0 + c1 * 8]);
        cp16(base + OFF_AL + r0 * ROW_STRIDE_B + c0 * 16, &g_Al[(size_t)(m0 + r0) * KDIM + k0 + c0 * 8]);
        cp16(base + OFF_AL + r1 * ROW_STRIDE_B + c1 * 16, &g_Al[(size_t)(m0 + r1) * KDIM + k0 + c1 * 8]);
        // B tiles (rows = output col, N-major)
        cp16(base + OFF_BH + r0 * ROW_STRIDE_B + c0 * 16, &g_Bh[(size_t)(n0 + r0) * KDIM + k0 + c0 * 8]);
        cp16(base + OFF_BH + r1 * ROW_STRIDE_B + c1 * 16, &g_Bh[(size_t)(n0 + r1) * KDIM + k0 + c1 * 8]);
        cp16(base + OFF_BL + r0 * ROW_STRIDE_B + c0 * 16, &g_Bl[(size_t)(n0 + r0) * KDIM + k0 + c0 * 8]);
        cp16(base + OFF_BL + r1 * ROW_STRIDE_B + c1 * 16, &g_Bl[(size_t)(n0 + r1) * KDIM + k0 + c1 * 8]);
        CP_COMMIT();
    };

    float acc[4][4][4];
    #pragma unroll
    for (int i = 0; i < 4; i++)
        #pragma unroll
        for (int j = 0; j < 4; j++)
            #pragma unroll
            for (int q = 0; q < 4; q++) acc[i][j][q] = 0.f;

    issue_stage(0);

    const int fr = lane >> 2;         // fragment row within 16 (0..7)
    const int fc = (lane & 3) * 2;    // fragment k-pair base (0,2,4,6)

    #pragma unroll 1
    for (int s = 0; s < NSTAGE; s++) {
        if (s + 1 < NSTAGE) issue_stage(s + 1);
        if (s + 1 < NSTAGE) { CP_WAIT(1); } else { CP_WAIT(0); }
        __syncthreads();

        const uint32_t base = sb + (s & 1) * STAGE_B;
        #pragma unroll
        for (int ksub = 0; ksub < 2; ksub++) {
            const uint32_t kb = (ksub * 16 + fc) * 2;   // byte offset in row
            uint32_t aH[4][4], aL[4][4], bH[4][2], bL[4][2];
            #pragma unroll
            for (int mt = 0; mt < 4; mt++) {
                const uint32_t ra = base + (warp_m * 64 + mt * 16 + fr) * ROW_STRIDE_B + kb;
                asm volatile("ld.shared.b32 %0, [%1];" : "=r"(aH[mt][0]) : "r"(ra + OFF_AH));
                asm volatile("ld.shared.b32 %0, [%1];" : "=r"(aH[mt][1]) : "r"(ra + OFF_AH + 8 * ROW_STRIDE_B));
                asm volatile("ld.shared.b32 %0, [%1];" : "=r"(aH[mt][2]) : "r"(ra + OFF_AH + 16));
                asm volatile("ld.shared.b32 %0, [%1];" : "=r"(aH[mt][3]) : "r"(ra + OFF_AH + 8 * ROW_STRIDE_B + 16));
                asm volatile("ld.shared.b32 %0, [%1];" : "=r"(aL[mt][0]) : "r"(ra + OFF_AL));
                asm volatile("ld.shared.b32 %0, [%1];" : "=r"(aL[mt][1]) : "r"(ra + OFF_AL + 8 * ROW_STRIDE_B));
                asm volatile("ld.shared.b32 %0, [%1];" : "=r"(aL[mt][2]) : "r"(ra + OFF_AL + 16));
                asm volatile("ld.shared.b32 %0, [%1];" : "=r"(aL[mt][3]) : "r"(ra + OFF_AL + 8 * ROW_STRIDE_B + 16));
            }
            #pragma unroll
            for (int nt = 0; nt < 4; nt++) {
                const uint32_t rb = base + (warp_n * 32 + nt * 8 + fr) * ROW_STRIDE_B + kb;
                asm volatile("ld.shared.b32 %0, [%1];" : "=r"(bH[nt][0]) : "r"(rb + OFF_BH));
                asm volatile("ld.shared.b32 %0, [%1];" : "=r"(bH[nt][1]) : "r"(rb + OFF_BH + 16));
                asm volatile("ld.shared.b32 %0, [%1];" : "=r"(bL[nt][0]) : "r"(rb + OFF_BL));
                asm volatile("ld.shared.b32 %0, [%1];" : "=r"(bL[nt][1]) : "r"(rb + OFF_BL + 16));
            }
            #pragma unroll
            for (int mt = 0; mt < 4; mt++)
                #pragma unroll
                for (int nt = 0; nt < 4; nt++) {
                    mma_bf16(acc[mt][nt], aH[mt], bH[nt]);
                    mma_bf16(acc[mt][nt], aH[mt], bL[nt]);
                    mma_bf16(acc[mt][nt], aL[mt], bH[nt]);
                }
        }
        __syncthreads();
    }

    // write pre-activations
    #pragma unroll
    for (int mt = 0; mt < 4; mt++) {
        const int row = m0 + warp_m * 64 + mt * 16 + fr;
        #pragma unroll
        for (int nt = 0; nt < 4; nt++) {
            const int col = n0 + warp_n * 32 + nt * 8 + fc;
            float2 v0 = {acc[mt][nt][0], acc[mt][nt][1]};
            float2 v1 = {acc[mt][nt][2], acc[mt][nt][3]};
            *(float2*)&g_P[(size_t)row * NTOT + col] = v0;
            *(float2*)&g_P[(size_t)(row + 8) * NTOT + col] = v1;
        }
    }
}

// ---------------- gate epilogue ----------------
__global__ __launch_bounds__(256) void epilogue_kernel(
    const float* __restrict__ cell,
    const float* __restrict__ bfp, const float* __restrict__ bip,
    const float* __restrict__ bcp, const float* __restrict__ bop,
    float* __restrict__ out_h, float* __restrict__ out_c)
{
    const int idx = blockIdx.x * 256 + threadIdx.x;  // over 4096*256
    const int b  = idx >> 8;
    const int u4 = (idx & 255) << 2;
    const size_t pbase = (size_t)b * NTOT + u4;
    const float4 pf = *(const float4*)&g_P[pbase];
    const float4 pi = *(const float4*)&g_P[pbase + 1024];
    const float4 pc = *(const float4*)&g_P[pbase + 2048];
    const float4 po = *(const float4*)&g_P[pbase + 3072];
    const float4 Bf = *(const float4*)&bfp[u4];
    const float4 Bi = *(const float4*)&bip[u4];
    const float4 Bc = *(const float4*)&bcp[u4];
    const float4 Bo = *(const float4*)&bop[u4];
    const float4 cp = *(const float4*)&cell[(size_t)b * UNITS + u4];

    float4 nh, nc;
    {
        const float f  = sig_(pf.x + Bf.x), ig = sig_(pi.x + Bi.x);
        const float cc = tanh_(pc.x + Bc.x), o = sig_(po.x + Bo.x);
        nc.x = f * cp.x + ig * cc; nh.x = o * tanh_(nc.x);
    }
    {
        const float f  = sig_(pf.y + Bf.y), ig = sig_(pi.y + Bi.y);
        const float cc = tanh_(pc.y + Bc.y), o = sig_(po.y + Bo.y);
        nc.y = f * cp.y + ig * cc; nh.y = o * tanh_(nc.y);
    }
    {
        const float f  = sig_(pf.z + Bf.z), ig = sig_(pi.z + Bi.z);
        const float cc = tanh_(pc.z + Bc.z), o = sig_(po.z + Bo.z);
        nc.z = f * cp.z + ig * cc; nh.z = o * tanh_(nc.z);
    }
    {
        const float f  = sig_(pf.w + Bf.w), ig = sig_(pi.w + Bi.w);
        const float cc = tanh_(pc.w + Bc.w), o = sig_(po.w + Bo.w);
        nc.w = f * cp.w + ig * cc; nh.w = o * tanh_(nc.w);
    }
    *(float4*)&out_h[(size_t)b * UNITS + u4] = nh;
    *(float4*)&out_c[(size_t)b * UNITS + u4] = nc;
}

// ---------------- host launch ----------------
extern "C" void kernel_launch(void* const* d_in, const int* in_sizes, int n_in,
                              void* d_out, int out_size) {
    const float* inp  = (const float*)d_in[0];
    const float* hid  = (const float*)d_in[1];
    const float* cell = (const float*)d_in[2];
    const float* Wf   = (const float*)d_in[3];
    const float* bf   = (const float*)d_in[4];
    const float* Wi   = (const float*)d_in[5];
    const float* bi   = (const float*)d_in[6];
    const float* Wc   = (const float*)d_in[7];
    const float* bc   = (const float*)d_in[8];
    const float* Wo   = (const float*)d_in[9];
    const float* bo   = (const float*)d_in[10];

    float* out_h = (float*)d_out;
    float* out_c = out_h + (size_t)BATCH * UNITS;

    cudaFuncSetAttribute(gemm_kernel,
                         cudaFuncAttributeMaxDynamicSharedMemorySize, SMEM_TOTAL);

    split_a_kernel<<<(BATCH * (KDIM / 4)) / 256, 256>>>(hid, inp);
    split_b_kernel<<<dim3(UNITS / 32, KDIM / 32, 4), 256>>>(Wf, Wi, Wc, Wo);
    gemm_kernel<<<dim3(NTOT / BN, BATCH / BM), 256, SMEM_TOTAL>>>();
    epilogue_kernel<<<(BATCH * UNITS / 4) / 256, 256>>>(cell, bf, bi, bc, bo, out_h, out_c);
}

// round 4
// speedup vs baseline: 2.1274x; 1.0433x over previous
#include <cuda_runtime.h>
#include <cuda_bf16.h>
#include <cstdint>
#include <math.h>

// LSTM cell: fused bf16 mma.sync GEMM (3-product bf16 split) + in-kernel gate epilogue.
// CTA tile: 128 batch rows x 32 units x 4 gates (BN=128 in gemm space).
// A = split(concat(hidden,inputs)) [4096 x 2048]; B = split(W^T) N-major [4096 x 2048].

#define BATCH 4096
#define UNITS 1024
#define KDIM  2048

#define BM 128
#define BNU 32              // units per CTA (x4 gates = 128 gemm cols)
#define BK 32
#define NSTAGE (KDIM / BK)  // 64
#define NBUF 3

#define ROW_B   80                      // 64B data + 16B pad (LDSM conflict-free)
#define TILE_B  (128 * ROW_B)           // 10240
#define OFF_AH  0
#define OFF_AL  TILE_B
#define OFF_BH  (2 * TILE_B)
#define OFF_BL  (3 * TILE_B)
#define STAGE_B (4 * TILE_B)            // 40960
#define SMEM_TOTAL (NBUF * STAGE_B)     // 122880

#define PS_STRIDE 132                   // floats, epilogue scratch stride

// ---------------- device scratch ----------------
__device__ __nv_bfloat16 g_Ah[(size_t)BATCH * KDIM];
__device__ __nv_bfloat16 g_Al[(size_t)BATCH * KDIM];
__device__ __nv_bfloat16 g_Bh[(size_t)4 * UNITS * KDIM];   // row = gate*1024 + n
__device__ __nv_bfloat16 g_Bl[(size_t)4 * UNITS * KDIM];

// ---------------- helpers ----------------
__device__ __forceinline__ uint32_t smem_u32(const void* p) {
    uint32_t a;
    asm("{ .reg .u64 t; cvta.to.shared.u64 t, %1; cvt.u32.u64 %0, t; }" : "=r"(a) : "l"(p));
    return a;
}
__device__ __forceinline__ void cp16(uint32_t dst, const void* src) {
    asm volatile("cp.async.cg.shared.global [%0], [%1], 16;" :: "r"(dst), "l"(src));
}
#define CP_COMMIT() asm volatile("cp.async.commit_group;" ::: "memory")
#define CP_WAIT(n)  asm volatile("cp.async.wait_group %0;" :: "n"(n) : "memory")

#define LDSM4(r0, r1, r2, r3, addr) \
    asm volatile("ldmatrix.sync.aligned.m8n8.x4.shared.b16 {%0,%1,%2,%3}, [%4];" \
        : "=r"(r0), "=r"(r1), "=r"(r2), "=r"(r3) : "r"(addr))

__device__ __forceinline__ void mma_bf16(float* c, const uint32_t* a, const uint32_t* b) {
    asm volatile(
        "mma.sync.aligned.m16n8k16.row.col.f32.bf16.bf16.f32 "
        "{%0,%1,%2,%3}, {%4,%5,%6,%7}, {%8,%9}, {%0,%1,%2,%3};"
        : "+f"(c[0]), "+f"(c[1]), "+f"(c[2]), "+f"(c[3])
        : "r"(a[0]), "r"(a[1]), "r"(a[2]), "r"(a[3]), "r"(b[0]), "r"(b[1]));
}

__device__ __forceinline__ float sig_(float x) {
    x = fminf(fmaxf(x, -30.f), 30.f);
    return __fdividef(1.f, 1.f + __expf(-x));
}
__device__ __forceinline__ float tanh_(float x) {
    x = fminf(fmaxf(x, -15.f), 15.f);
    float e = __expf(2.f * x);
    return __fdividef(e - 1.f, e + 1.f);
}

// ---------------- split precompute ----------------
__global__ __launch_bounds__(256) void split_a_kernel(
    const float* __restrict__ hid, const float* __restrict__ inp)
{
    int i4 = blockIdx.x * 256 + threadIdx.x;   // float4 index over [4096][512]
    int row = i4 >> 9;
    int c4  = i4 & 511;
    const float4 v = (c4 < 256)
        ? *(const float4*)&hid[(size_t)row * 1024 + c4 * 4]
        : *(const float4*)&inp[(size_t)row * 1024 + (c4 - 256) * 4];
    __nv_bfloat16 h[4], l[4];
    const float vv[4] = {v.x, v.y, v.z, v.w};
    #pragma unroll
    for (int j = 0; j < 4; j++) {
        h[j] = __float2bfloat16_rn(vv[j]);
        l[j] = __float2bfloat16_rn(vv[j] - __bfloat162float(h[j]));
    }
    size_t o = (size_t)row * KDIM + c4 * 4;
    *(uint2*)&g_Ah[o] = *(uint2*)h;
    *(uint2*)&g_Al[o] = *(uint2*)l;
}

__global__ __launch_bounds__(256) void split_b_kernel(
    const float* __restrict__ Wf, const float* __restrict__ Wi,
    const float* __restrict__ Wc, const float* __restrict__ Wo)
{
    __shared__ float tile[32][33];
    const int g = blockIdx.z;
    const float* W = (g == 0) ? Wf : (g == 1) ? Wi : (g == 2) ? Wc : Wo;
    const int n0 = blockIdx.x * 32;
    const int k0 = blockIdx.y * 32;
    const int tx = threadIdx.x & 31;
    const int ty = threadIdx.x >> 5;   // 0..7
    #pragma unroll
    for (int j = 0; j < 4; j++)
        tile[ty + 8 * j][tx] = W[(size_t)(k0 + ty + 8 * j) * UNITS + n0 + tx];
    __syncthreads();
    const int n_l = threadIdx.x >> 3;        // 0..31
    const int kq  = (threadIdx.x & 7) * 4;   // 0..28
    __nv_bfloat16 h[4], l[4];
    #pragma unroll
    for (int j = 0; j < 4; j++) {
        float v = tile[kq + j][n_l];
        h[j] = __float2bfloat16_rn(v);
        l[j] = __float2bfloat16_rn(v - __bfloat162float(h[j]));
    }
    size_t o = ((size_t)g * UNITS + n0 + n_l) * KDIM + k0 + kq;
    *(uint2*)&g_Bh[o] = *(uint2*)h;
    *(uint2*)&g_Bl[o] = *(uint2*)l;
}

// ---------------- fused GEMM + epilogue ----------------
__global__ __launch_bounds__(256, 1) void gemm_kernel(
    const float* __restrict__ cell,
    const float* __restrict__ bfp, const float* __restrict__ bip,
    const float* __restrict__ bcp, const float* __restrict__ bop,
    float* __restrict__ out_h, float* __restrict__ out_c)
{
    extern __shared__ char smem[];
    const uint32_t sb = smem_u32(smem);
    const int tid  = threadIdx.x;
    const int wid  = tid >> 5;
    const int lane = tid & 31;
    const int warp_m = wid & 1;    // 64 rows each
    const int gate   = wid >> 1;   // 0..3 -> 32 cols within its gate
    const int m0 = blockIdx.y * BM;
    const int n0 = blockIdx.x * BNU;

    // loader mapping: per array 512 x 16B chunks, 2 per thread
    const int r0 = tid >> 2,          c0 = tid & 3;
    const int r1 = (tid + 256) >> 2,  c1 = tid & 3;   // (tid+256)&3 == tid&3

    // B smem row -> global row
    const size_t bg0 = (size_t)((r0 >> 5) * UNITS + n0 + (r0 & 31)) * KDIM;
    const size_t bg1 = (size_t)((r1 >> 5) * UNITS + n0 + (r1 & 31)) * KDIM;
    const size_t ag0 = (size_t)(m0 + r0) * KDIM;
    const size_t ag1 = (size_t)(m0 + r1) * KDIM;

    auto issue_stage = [&](int s) {
        const int k0 = s * BK;
        const uint32_t base = sb + (s % NBUF) * STAGE_B;
        cp16(base + OFF_AH + r0 * ROW_B + c0 * 16, &g_Ah[ag0 + k0 + c0 * 8]);
        cp16(base + OFF_AH + r1 * ROW_B + c1 * 16, &g_Ah[ag1 + k0 + c1 * 8]);
        cp16(base + OFF_AL + r0 * ROW_B + c0 * 16, &g_Al[ag0 + k0 + c0 * 8]);
        cp16(base + OFF_AL + r1 * ROW_B + c1 * 16, &g_Al[ag1 + k0 + c1 * 8]);
        cp16(base + OFF_BH + r0 * ROW_B + c0 * 16, &g_Bh[bg0 + k0 + c0 * 8]);
        cp16(base + OFF_BH + r1 * ROW_B + c1 * 16, &g_Bh[bg1 + k0 + c1 * 8]);
        cp16(base + OFF_BL + r0 * ROW_B + c0 * 16, &g_Bl[bg0 + k0 + c0 * 8]);
        cp16(base + OFF_BL + r1 * ROW_B + c1 * 16, &g_Bl[bg1 + k0 + c1 * 8]);
        CP_COMMIT();
    };

    // ldmatrix lane addressing (byte offsets within tile)
    const uint32_t a_off = (uint32_t)((warp_m * 64 + (lane & 15)) * ROW_B + (lane >> 4) * 16);
    const uint32_t b_off = (uint32_t)((gate * 32 + (lane & 7) + ((lane >> 4) & 1) * 8) * ROW_B
                                      + ((lane >> 3) & 1) * 16);

    float acc[4][4][4];
    #pragma unroll
    for (int i = 0; i < 4; i++)
        #pragma unroll
        for (int j = 0; j < 4; j++)
            #pragma unroll
            for (int q = 0; q < 4; q++) acc[i][j][q] = 0.f;

    issue_stage(0);
    issue_stage(1);

    #pragma unroll 1
    for (int s = 0; s < NSTAGE; s++) {
        CP_WAIT(1);
        __syncthreads();
        if (s + 2 < NSTAGE) issue_stage(s + 2); else CP_COMMIT();

        const uint32_t base = sb + (s % NBUF) * STAGE_B;
        #pragma unroll
        for (int ksub = 0; ksub < 2; ksub++) {
            const uint32_t kb = ksub * 32;
            uint32_t aH[4][4], aL[4][4], bH[4][2], bL[4][2];
            #pragma unroll
            for (int mt = 0; mt < 4; mt++) {
                const uint32_t ra = base + a_off + mt * 16 * ROW_B + kb;
                LDSM4(aH[mt][0], aH[mt][1], aH[mt][2], aH[mt][3], ra + OFF_AH);
                LDSM4(aL[mt][0], aL[mt][1], aL[mt][2], aL[mt][3], ra + OFF_AL);
            }
            #pragma unroll
            for (int ntp = 0; ntp < 2; ntp++) {
                const uint32_t rb = base + b_off + ntp * 16 * ROW_B + kb;
                LDSM4(bH[ntp*2][0], bH[ntp*2][1], bH[ntp*2+1][0], bH[ntp*2+1][1], rb + OFF_BH);
                LDSM4(bL[ntp*2][0], bL[ntp*2][1], bL[ntp*2+1][0], bL[ntp*2+1][1], rb + OFF_BL);
            }
            #pragma unroll
            for (int mt = 0; mt < 4; mt++)
                #pragma unroll
                for (int nt = 0; nt < 4; nt++) {
                    mma_bf16(acc[mt][nt], aH[mt], bH[nt]);
                    mma_bf16(acc[mt][nt], aH[mt], bL[nt]);
                    mma_bf16(acc[mt][nt], aL[mt], bH[nt]);
                }
        }
    }
    __syncthreads();

    // ---- write accumulators to SMEM scratch P_s[128][132]
    float* P_s = (float*)smem;
    {
        const int fr = lane >> 2;
        const int fc = (lane & 3) * 2;
        #pragma unroll
        for (int mt = 0; mt < 4; mt++) {
            const int r = warp_m * 64 + mt * 16 + fr;
            #pragma unroll
            for (int nt = 0; nt < 4; nt++) {
                const int col = gate * 32 + nt * 8 + fc;
                *(float2*)&P_s[(size_t)r * PS_STRIDE + col] =
                    make_float2(acc[mt][nt][0], acc[mt][nt][1]);
                *(float2*)&P_s[(size_t)(r + 8) * PS_STRIDE + col] =
                    make_float2(acc[mt][nt][2], acc[mt][nt][3]);
            }
        }
    }
    __syncthreads();

    // ---- fused gate epilogue: 128 rows x 32 units
    #pragma unroll
    for (int it = 0; it < 4; it++) {
        const int idx = it * 256 + tid;       // over 128*8 float4 chunks
        const int r  = idx >> 3;
        const int u4 = (idx & 7) << 2;
        const float* pr = &P_s[(size_t)r * PS_STRIDE];
        const float4 pf = *(const float4*)&pr[u4];
        const float4 pi = *(const float4*)&pr[32 + u4];
        const float4 pc = *(const float4*)&pr[64 + u4];
        const float4 po = *(const float4*)&pr[96 + u4];
        const float4 Bf = *(const float4*)&bfp[n0 + u4];
        const float4 Bi = *(const float4*)&bip[n0 + u4];
        const float4 Bc = *(const float4*)&bcp[n0 + u4];
        const float4 Bo = *(const float4*)&bop[n0 + u4];
        const size_t go = (size_t)(m0 + r) * UNITS + n0 + u4;
        const float4 cp = *(const float4*)&cell[go];

        float4 nh, nc;
        {
            const float f = sig_(pf.x + Bf.x), ig = sig_(pi.x + Bi.x);
            const float cc = tanh_(pc.x + Bc.x), o = sig_(po.x + Bo.x);
            nc.x = f * cp.x + ig * cc; nh.x = o * tanh_(nc.x);
        }
        {
            const float f = sig_(pf.y + Bf.y), ig = sig_(pi.y + Bi.y);
            const float cc = tanh_(pc.y + Bc.y), o = sig_(po.y + Bo.y);
            nc.y = f * cp.y + ig * cc; nh.y = o * tanh_(nc.y);
        }
        {
            const float f = sig_(pf.z + Bf.z), ig = sig_(pi.z + Bi.z);
            const float cc = tanh_(pc.z + Bc.z), o = sig_(po.z + Bo.z);
            nc.z = f * cp.z + ig * cc; nh.z = o * tanh_(nc.z);
        }
        {
            const float f = sig_(pf.w + Bf.w), ig = sig_(pi.w + Bi.w);
            const float cc = tanh_(pc.w + Bc.w), o = sig_(po.w + Bo.w);
            nc.w = f * cp.w + ig * cc; nh.w = o * tanh_(nc.w);
        }
        *(float4*)&out_h[go] = nh;
        *(float4*)&out_c[go] = nc;
    }
}

// ---------------- host launch ----------------
extern "C" void kernel_launch(void* const* d_in, const int* in_sizes, int n_in,
                              void* d_out, int out_size) {
    const float* inp  = (const float*)d_in[0];
    const float* hid  = (const float*)d_in[1];
    const float* cell = (const float*)d_in[2];
    const float* Wf   = (const float*)d_in[3];
    const float* bf   = (const float*)d_in[4];
    const float* Wi   = (const float*)d_in[5];
    const float* bi   = (const float*)d_in[6];
    const float* Wc   = (const float*)d_in[7];
    const float* bc   = (const float*)d_in[8];
    const float* Wo   = (const float*)d_in[9];
    const float* bo   = (const float*)d_in[10];

    float* out_h = (float*)d_out;
    float* out_c = out_h + (size_t)BATCH * UNITS;

    cudaFuncSetAttribute(gemm_kernel,
                         cudaFuncAttributeMaxDynamicSharedMemorySize, SMEM_TOTAL);

    split_a_kernel<<<(BATCH * (KDIM / 4)) / 256, 256>>>(hid, inp);
    split_b_kernel<<<dim3(UNITS / 32, KDIM / 32, 4), 256>>>(Wf, Wi, Wc, Wo);
    gemm_kernel<<<dim3(UNITS / BNU, BATCH / BM), 256, SMEM_TOTAL>>>(
        cell, bf, bi, bc, bo, out_h, out_c);
}

// round 5
// speedup vs baseline: 2.9400x; 1.3820x over previous
#include <cuda_runtime.h>
#include <cuda_fp16.h>
#include <cstdint>
#include <math.h>

// LSTM cell: fused fp16 mma.sync GEMM (2-term fp16 split: (Ah+Al)*Bh) + fused gate epilogue.
// CTA tile: 128 batch rows x 32 units x 4 gates. A exact as fp16 pair; B fp16-rounded.

#define BATCH 4096
#define UNITS 1024
#define KDIM  2048

#define BM 128
#define BNU 32              // units per CTA (x4 gates = 128 gemm cols)
#define BK 32
#define NSTAGE (KDIM / BK)  // 64
#define NBUF 4

#define ROW_B   80                      // 64B data + 16B pad (LDSM conflict-free)
#define TILE_B  (128 * ROW_B)           // 10240
#define OFF_AH  0
#define OFF_AL  TILE_B
#define OFF_BH  (2 * TILE_B)
#define STAGE_B (3 * TILE_B)            // 30720
#define SMEM_TOTAL (NBUF * STAGE_B)     // 122880

#define PS_STRIDE 132                   // floats, epilogue scratch stride

// ---------------- device scratch ----------------
__device__ __half g_Ah[(size_t)BATCH * KDIM];
__device__ __half g_Al[(size_t)BATCH * KDIM];
__device__ __half g_Bh[(size_t)4 * UNITS * KDIM];   // row = gate*1024 + n, k contiguous

// ---------------- helpers ----------------
__device__ __forceinline__ uint32_t smem_u32(const void* p) {
    uint32_t a;
    asm("{ .reg .u64 t; cvta.to.shared.u64 t, %1; cvt.u32.u64 %0, t; }" : "=r"(a) : "l"(p));
    return a;
}
__device__ __forceinline__ void cp16(uint32_t dst, const void* src) {
    asm volatile("cp.async.cg.shared.global [%0], [%1], 16;" :: "r"(dst), "l"(src));
}
#define CP_COMMIT() asm volatile("cp.async.commit_group;" ::: "memory")
#define CP_WAIT(n)  asm volatile("cp.async.wait_group %0;" :: "n"(n) : "memory")

#define LDSM4(r0, r1, r2, r3, addr) \
    asm volatile("ldmatrix.sync.aligned.m8n8.x4.shared.b16 {%0,%1,%2,%3}, [%4];" \
        : "=r"(r0), "=r"(r1), "=r"(r2), "=r"(r3) : "r"(addr))

__device__ __forceinline__ void mma_f16(float* c, const uint32_t* a, const uint32_t* b) {
    asm volatile(
        "mma.sync.aligned.m16n8k16.row.col.f32.f16.f16.f32 "
        "{%0,%1,%2,%3}, {%4,%5,%6,%7}, {%8,%9}, {%0,%1,%2,%3};"
        : "+f"(c[0]), "+f"(c[1]), "+f"(c[2]), "+f"(c[3])
        : "r"(a[0]), "r"(a[1]), "r"(a[2]), "r"(a[3]), "r"(b[0]), "r"(b[1]));
}

__device__ __forceinline__ float sig_(float x) {
    x = fminf(fmaxf(x, -30.f), 30.f);
    return __fdividef(1.f, 1.f + __expf(-x));
}
__device__ __forceinline__ float tanh_(float x) {
    x = fminf(fmaxf(x, -15.f), 15.f);
    float e = __expf(2.f * x);
    return __fdividef(e - 1.f, e + 1.f);
}

// ---------------- split precompute ----------------
__global__ __launch_bounds__(256) void split_a_kernel(
    const float* __restrict__ hid, const float* __restrict__ inp)
{
    int i4 = blockIdx.x * 256 + threadIdx.x;   // float4 index over [4096][512]
    int row = i4 >> 9;
    int c4  = i4 & 511;
    const float4 v = (c4 < 256)
        ? *(const float4*)&hid[(size_t)row * 1024 + c4 * 4]
        : *(const float4*)&inp[(size_t)row * 1024 + (c4 - 256) * 4];
    __half h[4], l[4];
    const float vv[4] = {v.x, v.y, v.z, v.w};
    #pragma unroll
    for (int j = 0; j < 4; j++) {
        h[j] = __float2half_rn(vv[j]);
        l[j] = __float2half_rn(vv[j] - __half2float(h[j]));
    }
    size_t o = (size_t)row * KDIM + c4 * 4;
    *(uint2*)&g_Ah[o] = *(uint2*)h;
    *(uint2*)&g_Al[o] = *(uint2*)l;
}

__global__ __launch_bounds__(256) void split_b_kernel(
    const float* __restrict__ Wf, const float* __restrict__ Wi,
    const float* __restrict__ Wc, const float* __restrict__ Wo)
{
    __shared__ float tile[32][33];
    const int g = blockIdx.z;
    const float* W = (g == 0) ? Wf : (g == 1) ? Wi : (g == 2) ? Wc : Wo;
    const int n0 = blockIdx.x * 32;
    const int k0 = blockIdx.y * 32;
    const int tx = threadIdx.x & 31;
    const int ty = threadIdx.x >> 5;   // 0..7
    #pragma unroll
    for (int j = 0; j < 4; j++)
        tile[ty + 8 * j][tx] = W[(size_t)(k0 + ty + 8 * j) * UNITS + n0 + tx];
    __syncthreads();
    const int n_l = threadIdx.x >> 3;        // 0..31
    const int kq  = (threadIdx.x & 7) * 4;   // 0..28
    __half h[4];
    #pragma unroll
    for (int j = 0; j < 4; j++)
        h[j] = __float2half_rn(tile[kq + j][n_l]);
    size_t o = ((size_t)g * UNITS + n0 + n_l) * KDIM + k0 + kq;
    *(uint2*)&g_Bh[o] = *(uint2*)h;
}

// ---------------- fused GEMM + epilogue ----------------
__global__ __launch_bounds__(256, 1) void gemm_kernel(
    const float* __restrict__ cell,
    const float* __restrict__ bfp, const float* __restrict__ bip,
    const float* __restrict__ bcp, const float* __restrict__ bop,
    float* __restrict__ out_h, float* __restrict__ out_c)
{
    extern __shared__ char smem[];
    const uint32_t sb = smem_u32(smem);
    const int tid  = threadIdx.x;
    const int wid  = tid >> 5;
    const int lane = tid & 31;
    const int warp_m = wid & 1;    // 64 rows each
    const int gate   = wid >> 1;   // 0..3 -> 32 cols within its gate
    const int m0 = blockIdx.y * BM;
    const int n0 = blockIdx.x * BNU;

    // loader mapping: per array 512 x 16B chunks, 2 per thread
    const int r0 = tid >> 2,          c0 = tid & 3;
    const int r1 = (tid + 256) >> 2,  c1 = tid & 3;

    const size_t bg0 = (size_t)((r0 >> 5) * UNITS + n0 + (r0 & 31)) * KDIM;
    const size_t bg1 = (size_t)((r1 >> 5) * UNITS + n0 + (r1 & 31)) * KDIM;
    const size_t ag0 = (size_t)(m0 + r0) * KDIM;
    const size_t ag1 = (size_t)(m0 + r1) * KDIM;

    auto issue_stage = [&](int s) {
        const int k0 = s * BK;
        const uint32_t base = sb + (s % NBUF) * STAGE_B;
        cp16(base + OFF_AH + r0 * ROW_B + c0 * 16, &g_Ah[ag0 + k0 + c0 * 8]);
        cp16(base + OFF_AH + r1 * ROW_B + c1 * 16, &g_Ah[ag1 + k0 + c1 * 8]);
        cp16(base + OFF_AL + r0 * ROW_B + c0 * 16, &g_Al[ag0 + k0 + c0 * 8]);
        cp16(base + OFF_AL + r1 * ROW_B + c1 * 16, &g_Al[ag1 + k0 + c1 * 8]);
        cp16(base + OFF_BH + r0 * ROW_B + c0 * 16, &g_Bh[bg0 + k0 + c0 * 8]);
        cp16(base + OFF_BH + r1 * ROW_B + c1 * 16, &g_Bh[bg1 + k0 + c1 * 8]);
        CP_COMMIT();
    };

    // ldmatrix lane addressing (byte offsets within tile)
    const uint32_t a_off = (uint32_t)((warp_m * 64 + (lane & 15)) * ROW_B + (lane >> 4) * 16);
    const uint32_t b_off = (uint32_t)((gate * 32 + (lane & 7) + ((lane >> 4) & 1) * 8) * ROW_B
                                      + ((lane >> 3) & 1) * 16);

    float acc[4][4][4];
    #pragma unroll
    for (int i = 0; i < 4; i++)
        #pragma unroll
        for (int j = 0; j < 4; j++)
            #pragma unroll
            for (int q = 0; q < 4; q++) acc[i][j][q] = 0.f;

    issue_stage(0);
    issue_stage(1);
    issue_stage(2);

    #pragma unroll 1
    for (int s = 0; s < NSTAGE; s++) {
        CP_WAIT(2);
        __syncthreads();
        if (s + 3 < NSTAGE) issue_stage(s + 3); else CP_COMMIT();

        const uint32_t base = sb + (s % NBUF) * STAGE_B;
        #pragma unroll
        for (int ksub = 0; ksub < 2; ksub++) {
            const uint32_t kb = ksub * 32;
            uint32_t aH[4][4], aL[4][4], bH[4][2];
            #pragma unroll
            for (int mt = 0; mt < 4; mt++) {
                const uint32_t ra = base + a_off + mt * 16 * ROW_B + kb;
                LDSM4(aH[mt][0], aH[mt][1], aH[mt][2], aH[mt][3], ra + OFF_AH);
                LDSM4(aL[mt][0], aL[mt][1], aL[mt][2], aL[mt][3], ra + OFF_AL);
            }
            #pragma unroll
            for (int ntp = 0; ntp < 2; ntp++) {
                const uint32_t rb = base + b_off + ntp * 16 * ROW_B + kb;
                LDSM4(bH[ntp*2][0], bH[ntp*2][1], bH[ntp*2+1][0], bH[ntp*2+1][1], rb + OFF_BH);
            }
            #pragma unroll
            for (int mt = 0; mt < 4; mt++)
                #pragma unroll
                for (int nt = 0; nt < 4; nt++) {
                    mma_f16(acc[mt][nt], aH[mt], bH[nt]);
                    mma_f16(acc[mt][nt], aL[mt], bH[nt]);
                }
        }
    }
    __syncthreads();

    // ---- write accumulators to SMEM scratch P_s[128][132]
    float* P_s = (float*)smem;
    {
        const int fr = lane >> 2;
        const int fc = (lane & 3) * 2;
        #pragma unroll
        for (int mt = 0; mt < 4; mt++) {
            const int r = warp_m * 64 + mt * 16 + fr;
            #pragma unroll
            for (int nt = 0; nt < 4; nt++) {
                const int col = gate * 32 + nt * 8 + fc;
                *(float2*)&P_s[(size_t)r * PS_STRIDE + col] =
                    make_float2(acc[mt][nt][0], acc[mt][nt][1]);
                *(float2*)&P_s[(size_t)(r + 8) * PS_STRIDE + col] =
                    make_float2(acc[mt][nt][2], acc[mt][nt][3]);
            }
        }
    }
    __syncthreads();

    // ---- fused gate epilogue: 128 rows x 32 units
    #pragma unroll
    for (int it = 0; it < 4; it++) {
        const int idx = it * 256 + tid;       // over 128*8 float4 chunks
        const int r  = idx >> 3;
        const int u4 = (idx & 7) << 2;
        const float* pr = &P_s[(size_t)r * PS_STRIDE];
        const float4 pf = *(const float4*)&pr[u4];
        const float4 pi = *(const float4*)&pr[32 + u4];
        const float4 pc = *(const float4*)&pr[64 + u4];
        const float4 po = *(const float4*)&pr[96 + u4];
        const float4 Bf = *(const float4*)&bfp[n0 + u4];
        const float4 Bi = *(const float4*)&bip[n0 + u4];
        const float4 Bc = *(const float4*)&bcp[n0 + u4];
        const float4 Bo = *(const float4*)&bop[n0 + u4];
        const size_t go = (size_t)(m0 + r) * UNITS + n0 + u4;
        const float4 cp = *(const float4*)&cell[go];

        float4 nh, nc;
        {
            const float f = sig_(pf.x + Bf.x), ig = sig_(pi.x + Bi.x);
            const float cc = tanh_(pc.x + Bc.x), o = sig_(po.x + Bo.x);
            nc.x = f * cp.x + ig * cc; nh.x = o * tanh_(nc.x);
        }
        {
            const float f = sig_(pf.y + Bf.y), ig = sig_(pi.y + Bi.y);
            const float cc = tanh_(pc.y + Bc.y), o = sig_(po.y + Bo.y);
            nc.y = f * cp.y + ig * cc; nh.y = o * tanh_(nc.y);
        }
        {
            const float f = sig_(pf.z + Bf.z), ig = sig_(pi.z + Bi.z);
            const float cc = tanh_(pc.z + Bc.z), o = sig_(po.z + Bo.z);
            nc.z = f * cp.z + ig * cc; nh.z = o * tanh_(nc.z);
        }
        {
            const float f = sig_(pf.w + Bf.w), ig = sig_(pi.w + Bi.w);
            const float cc = tanh_(pc.w + Bc.w), o = sig_(po.w + Bo.w);
            nc.w = f * cp.w + ig * cc; nh.w = o * tanh_(nc.w);
        }
        *(float4*)&out_h[go] = nh;
        *(float4*)&out_c[go] = nc;
    }
}

// ---------------- host launch ----------------
extern "C" void kernel_launch(void* const* d_in, const int* in_sizes, int n_in,
                              void* d_out, int out_size) {
    const float* inp  = (const float*)d_in[0];
    const float* hid  = (const float*)d_in[1];
    const float* cell = (const float*)d_in[2];
    const float* Wf   = (const float*)d_in[3];
    const float* bf   = (const float*)d_in[4];
    const float* Wi   = (const float*)d_in[5];
    const float* bi   = (const float*)d_in[6];
    const float* Wc   = (const float*)d_in[7];
    const float* bc   = (const float*)d_in[8];
    const float* Wo   = (const float*)d_in[9];
    const float* bo   = (const float*)d_in[10];

    float* out_h = (float*)d_out;
    float* out_c = out_h + (size_t)BATCH * UNITS;

    cudaFuncSetAttribute(gemm_kernel,
                         cudaFuncAttributeMaxDynamicSharedMemorySize, SMEM_TOTAL);

    split_a_kernel<<<(BATCH * (KDIM / 4)) / 256, 256>>>(hid, inp);
    split_b_kernel<<<dim3(UNITS / 32, KDIM / 32, 4), 256>>>(Wf, Wi, Wc, Wo);
    gemm_kernel<<<dim3(UNITS / BNU, BATCH / BM), 256, SMEM_TOTAL>>>(
        cell, bf, bi, bc, bo, out_h, out_c);
}

// round 6
// speedup vs baseline: 4.4563x; 1.5158x over previous
#include <cuda_runtime.h>
#include <cuda_fp16.h>
#include <cstdint>
#include <math.h>

// LSTM cell: plain fp16 mma.sync GEMM (single product, fp32 accum) + fused gate epilogue.
// Calibrated error model: B-only rounding gave rel_err 1.67e-4; A+B rounding ~2.4e-4 < 1e-3.
// CTA tile: 128 batch rows x 32 units x 4 gates (128 gemm cols).

#define BATCH 4096
#define UNITS 1024
#define KDIM  2048

#define BM 128
#define BNU 32              // units per CTA (x4 gates = 128 gemm cols)
#define BK 32
#define NSTAGE (KDIM / BK)  // 64
#define NBUF 5
#define PREF 4              // stages in flight

#define ROW_B   80                      // 64B data + 16B pad (LDSM conflict-free)
#define TILE_B  (128 * ROW_B)           // 10240
#define OFF_AH  0
#define OFF_BH  TILE_B
#define STAGE_B (2 * TILE_B)            // 20480
#define SMEM_TOTAL (NBUF * STAGE_B)     // 102400

#define PS_STRIDE 132                   // floats, epilogue scratch stride

// ---------------- device scratch ----------------
__device__ __half g_Ah[(size_t)BATCH * KDIM];
__device__ __half g_Bh[(size_t)4 * UNITS * KDIM];   // row = gate*1024 + n, k contiguous

// ---------------- helpers ----------------
__device__ __forceinline__ uint32_t smem_u32(const void* p) {
    uint32_t a;
    asm("{ .reg .u64 t; cvta.to.shared.u64 t, %1; cvt.u32.u64 %0, t; }" : "=r"(a) : "l"(p));
    return a;
}
__device__ __forceinline__ void cp16(uint32_t dst, const void* src) {
    asm volatile("cp.async.cg.shared.global [%0], [%1], 16;" :: "r"(dst), "l"(src));
}
#define CP_COMMIT() asm volatile("cp.async.commit_group;" ::: "memory")
#define CP_WAIT(n)  asm volatile("cp.async.wait_group %0;" :: "n"(n) : "memory")

#define LDSM4(r0, r1, r2, r3, addr) \
    asm volatile("ldmatrix.sync.aligned.m8n8.x4.shared.b16 {%0,%1,%2,%3}, [%4];" \
        : "=r"(r0), "=r"(r1), "=r"(r2), "=r"(r3) : "r"(addr))

__device__ __forceinline__ void mma_f16(float* c, const uint32_t* a, const uint32_t* b) {
    asm volatile(
        "mma.sync.aligned.m16n8k16.row.col.f32.f16.f16.f32 "
        "{%0,%1,%2,%3}, {%4,%5,%6,%7}, {%8,%9}, {%0,%1,%2,%3};"
        : "+f"(c[0]), "+f"(c[1]), "+f"(c[2]), "+f"(c[3])
        : "r"(a[0]), "r"(a[1]), "r"(a[2]), "r"(a[3]), "r"(b[0]), "r"(b[1]));
}

__device__ __forceinline__ float sig_(float x) {
    x = fminf(fmaxf(x, -30.f), 30.f);
    return __fdividef(1.f, 1.f + __expf(-x));
}
__device__ __forceinline__ float tanh_(float x) {
    x = fminf(fmaxf(x, -15.f), 15.f);
    float e = __expf(2.f * x);
    return __fdividef(e - 1.f, e + 1.f);
}

// ---------------- precompute: fp16 round of A (concat) and W^T ----------------
__global__ __launch_bounds__(256) void split_a_kernel(
    const float* __restrict__ hid, const float* __restrict__ inp)
{
    int i4 = blockIdx.x * 256 + threadIdx.x;   // float4 index over [4096][512]
    int row = i4 >> 9;
    int c4  = i4 & 511;
    const float4 v = (c4 < 256)
        ? *(const float4*)&hid[(size_t)row * 1024 + c4 * 4]
        : *(const float4*)&inp[(size_t)row * 1024 + (c4 - 256) * 4];
    __half h[4];
    h[0] = __float2half_rn(v.x);
    h[1] = __float2half_rn(v.y);
    h[2] = __float2half_rn(v.z);
    h[3] = __float2half_rn(v.w);
    *(uint2*)&g_Ah[(size_t)row * KDIM + c4 * 4] = *(uint2*)h;
}

__global__ __launch_bounds__(256) void split_b_kernel(
    const float* __restrict__ Wf, const float* __restrict__ Wi,
    const float* __restrict__ Wc, const float* __restrict__ Wo)
{
    __shared__ float tile[32][33];
    const int g = blockIdx.z;
    const float* W = (g == 0) ? Wf : (g == 1) ? Wi : (g == 2) ? Wc : Wo;
    const int n0 = blockIdx.x * 32;
    const int k0 = blockIdx.y * 32;
    const int tx = threadIdx.x & 31;
    const int ty = threadIdx.x >> 5;   // 0..7
    #pragma unroll
    for (int j = 0; j < 4; j++)
        tile[ty + 8 * j][tx] = W[(size_t)(k0 + ty + 8 * j) * UNITS + n0 + tx];
    __syncthreads();
    const int n_l = threadIdx.x >> 3;        // 0..31
    const int kq  = (threadIdx.x & 7) * 4;   // 0..28
    __half h[4];
    #pragma unroll
    for (int j = 0; j < 4; j++)
        h[j] = __float2half_rn(tile[kq + j][n_l]);
    size_t o = ((size_t)g * UNITS + n0 + n_l) * KDIM + k0 + kq;
    *(uint2*)&g_Bh[o] = *(uint2*)h;
}

// ---------------- fused GEMM + epilogue ----------------
__global__ __launch_bounds__(256, 1) void gemm_kernel(
    const float* __restrict__ cell,
    const float* __restrict__ bfp, const float* __restrict__ bip,
    const float* __restrict__ bcp, const float* __restrict__ bop,
    float* __restrict__ out_h, float* __restrict__ out_c)
{
    extern __shared__ char smem[];
    const uint32_t sb = smem_u32(smem);
    const int tid  = threadIdx.x;
    const int wid  = tid >> 5;
    const int lane = tid & 31;
    const int warp_m = wid & 1;    // 64 rows each
    const int gate   = wid >> 1;   // 0..3 -> 32 cols within its gate
    const int m0 = blockIdx.y * BM;
    const int n0 = blockIdx.x * BNU;

    // loader mapping: per array 512 x 16B chunks, 2 per thread
    const int r0 = tid >> 2,          c0 = tid & 3;
    const int r1 = (tid + 256) >> 2,  c1 = tid & 3;

    const size_t bg0 = (size_t)((r0 >> 5) * UNITS + n0 + (r0 & 31)) * KDIM;
    const size_t bg1 = (size_t)((r1 >> 5) * UNITS + n0 + (r1 & 31)) * KDIM;
    const size_t ag0 = (size_t)(m0 + r0) * KDIM;
    const size_t ag1 = (size_t)(m0 + r1) * KDIM;

    auto issue_stage = [&](int s) {
        const int k0 = s * BK;
        const uint32_t base = sb + (s % NBUF) * STAGE_B;
        cp16(base + OFF_AH + r0 * ROW_B + c0 * 16, &g_Ah[ag0 + k0 + c0 * 8]);
        cp16(base + OFF_AH + r1 * ROW_B + c1 * 16, &g_Ah[ag1 + k0 + c1 * 8]);
        cp16(base + OFF_BH + r0 * ROW_B + c0 * 16, &g_Bh[bg0 + k0 + c0 * 8]);
        cp16(base + OFF_BH + r1 * ROW_B + c1 * 16, &g_Bh[bg1 + k0 + c1 * 8]);
        CP_COMMIT();
    };

    // ldmatrix lane addressing (byte offsets within tile)
    const uint32_t a_off = (uint32_t)((warp_m * 64 + (lane & 15)) * ROW_B + (lane >> 4) * 16);
    const uint32_t b_off = (uint32_t)((gate * 32 + (lane & 7) + ((lane >> 4) & 1) * 8) * ROW_B
                                      + ((lane >> 3) & 1) * 16);

    float acc[4][4][4];
    #pragma unroll
    for (int i = 0; i < 4; i++)
        #pragma unroll
        for (int j = 0; j < 4; j++)
            #pragma unroll
            for (int q = 0; q < 4; q++) acc[i][j][q] = 0.f;

    issue_stage(0);
    issue_stage(1);
    issue_stage(2);
    issue_stage(3);

    #pragma unroll 1
    for (int s = 0; s < NSTAGE; s++) {
        CP_WAIT(3);
        __syncthreads();
        if (s + PREF < NSTAGE) issue_stage(s + PREF); else CP_COMMIT();

        const uint32_t base = sb + (s % NBUF) * STAGE_B;
        #pragma unroll
        for (int ksub = 0; ksub < 2; ksub++) {
            const uint32_t kb = ksub * 32;
            uint32_t aH[4][4], bH[4][2];
            #pragma unroll
            for (int mt = 0; mt < 4; mt++) {
                const uint32_t ra = base + a_off + mt * 16 * ROW_B + kb;
                LDSM4(aH[mt][0], aH[mt][1], aH[mt][2], aH[mt][3], ra + OFF_AH);
            }
            #pragma unroll
            for (int ntp = 0; ntp < 2; ntp++) {
                const uint32_t rb = base + b_off + ntp * 16 * ROW_B + kb;
                LDSM4(bH[ntp*2][0], bH[ntp*2][1], bH[ntp*2+1][0], bH[ntp*2+1][1], rb + OFF_BH);
            }
            #pragma unroll
            for (int mt = 0; mt < 4; mt++)
                #pragma unroll
                for (int nt = 0; nt < 4; nt++)
                    mma_f16(acc[mt][nt], aH[mt], bH[nt]);
        }
    }
    __syncthreads();

    // ---- write accumulators to SMEM scratch P_s[128][132]
    float* P_s = (float*)smem;
    {
        const int fr = lane >> 2;
        const int fc = (lane & 3) * 2;
        #pragma unroll
        for (int mt = 0; mt < 4; mt++) {
            const int r = warp_m * 64 + mt * 16 + fr;
            #pragma unroll
            for (int nt = 0; nt < 4; nt++) {
                const int col = gate * 32 + nt * 8 + fc;
                *(float2*)&P_s[(size_t)r * PS_STRIDE + col] =
                    make_float2(acc[mt][nt][0], acc[mt][nt][1]);
                *(float2*)&P_s[(size_t)(r + 8) * PS_STRIDE + col] =
                    make_float2(acc[mt][nt][2], acc[mt][nt][3]);
            }
        }
    }
    __syncthreads();

    // ---- fused gate epilogue: 128 rows x 32 units
    #pragma unroll
    for (int it = 0; it < 4; it++) {
        const int idx = it * 256 + tid;       // over 128*8 float4 chunks
        const int r  = idx >> 3;
        const int u4 = (idx & 7) << 2;
        const float* pr = &P_s[(size_t)r * PS_STRIDE];
        const float4 pf = *(const float4*)&pr[u4];
        const float4 pi = *(const float4*)&pr[32 + u4];
        const float4 pc = *(const float4*)&pr[64 + u4];
        const float4 po = *(const float4*)&pr[96 + u4];
        const float4 Bf = *(const float4*)&bfp[n0 + u4];
        const float4 Bi = *(const float4*)&bip[n0 + u4];
        const float4 Bc = *(const float4*)&bcp[n0 + u4];
        const float4 Bo = *(const float4*)&bop[n0 + u4];
        const size_t go = (size_t)(m0 + r) * UNITS + n0 + u4;
        const float4 cp = *(const float4*)&cell[go];

        float4 nh, nc;
        {
            const float f = sig_(pf.x + Bf.x), ig = sig_(pi.x + Bi.x);
            const float cc = tanh_(pc.x + Bc.x), o = sig_(po.x + Bo.x);
            nc.x = f * cp.x + ig * cc; nh.x = o * tanh_(nc.x);
        }
        {
            const float f = sig_(pf.y + Bf.y), ig = sig_(pi.y + Bi.y);
            const float cc = tanh_(pc.y + Bc.y), o = sig_(po.y + Bo.y);
            nc.y = f * cp.y + ig * cc; nh.y = o * tanh_(nc.y);
        }
        {
            const float f = sig_(pf.z + Bf.z), ig = sig_(pi.z + Bi.z);
            const float cc = tanh_(pc.z + Bc.z), o = sig_(po.z + Bo.z);
            nc.z = f * cp.z + ig * cc; nh.z = o * tanh_(nc.z);
        }
        {
            const float f = sig_(pf.w + Bf.w), ig = sig_(pi.w + Bi.w);
            const float cc = tanh_(pc.w + Bc.w), o = sig_(po.w + Bo.w);
            nc.w = f * cp.w + ig * cc; nh.w = o * tanh_(nc.w);
        }
        *(float4*)&out_h[go] = nh;
        *(float4*)&out_c[go] = nc;
    }
}

// ---------------- host launch ----------------
extern "C" void kernel_launch(void* const* d_in, const int* in_sizes, int n_in,
                              void* d_out, int out_size) {
    const float* inp  = (const float*)d_in[0];
    const float* hid  = (const float*)d_in[1];
    const float* cell = (const float*)d_in[2];
    const float* Wf   = (const float*)d_in[3];
    const float* bf   = (const float*)d_in[4];
    const float* Wi   = (const float*)d_in[5];
    const float* bi   = (const float*)d_in[6];
    const float* Wc   = (const float*)d_in[7];
    const float* bc   = (const float*)d_in[8];
    const float* Wo   = (const float*)d_in[9];
    const float* bo   = (const float*)d_in[10];

    float* out_h = (float*)d_out;
    float* out_c = out_h + (size_t)BATCH * UNITS;

    cudaFuncSetAttribute(gemm_kernel,
                         cudaFuncAttributeMaxDynamicSharedMemorySize, SMEM_TOTAL);

    split_a_kernel<<<(BATCH * (KDIM / 4)) / 256, 256>>>(hid, inp);
    split_b_kernel<<<dim3(UNITS / 32, KDIM / 32, 4), 256>>>(Wf, Wi, Wc, Wo);
    gemm_kernel<<<dim3(UNITS / BNU, BATCH / BM), 256, SMEM_TOTAL>>>(
        cell, bf, bi, bc, bo, out_h, out_c);
}

// round 7
// speedup vs baseline: 6.4704x; 1.4520x over previous
#include <cuda_runtime.h>
#include <cuda_fp16.h>
#include <cstdint>
#include <math.h>

// LSTM cell: plain fp16 mma.sync GEMM + register-direct fused gate epilogue.
// Warp tiling: 2 warps in M (64 rows each) x 4 warps in N-units (8 units each);
// per-warp nt dimension = the 4 gates -> each thread holds f,i,c,o for its
// (row, unit) pairs in registers; epilogue needs no SMEM.
// 2 CTAs/SM (NBUF=2, BK=64, 72KB smem, launch_bounds(256,2)).

#define BATCH 4096
#define UNITS 1024
#define KDIM  2048

#define BM 128
#define BNU 32              // units per CTA (x4 gates = 128 gemm cols)
#define BK 64
#define NSTAGE (KDIM / BK)  // 32
#define NBUF 2

#define ROW_B   144                     // 128B data + 16B pad (conflict-free: 144/16=9 odd)
#define TILE_B  (128 * ROW_B)           // 18432
#define OFF_AH  0
#define OFF_BH  TILE_B
#define STAGE_B (2 * TILE_B)            // 36864
#define SMEM_TOTAL (NBUF * STAGE_B)     // 73728

// ---------------- device scratch ----------------
__device__ __half g_Ah[(size_t)BATCH * KDIM];
__device__ __half g_Bh[(size_t)4 * UNITS * KDIM];   // row = gate*1024 + n, k contiguous

// ---------------- helpers ----------------
__device__ __forceinline__ uint32_t smem_u32(const void* p) {
    uint32_t a;
    asm("{ .reg .u64 t; cvta.to.shared.u64 t, %1; cvt.u32.u64 %0, t; }" : "=r"(a) : "l"(p));
    return a;
}
__device__ __forceinline__ void cp16(uint32_t dst, const void* src) {
    asm volatile("cp.async.cg.shared.global [%0], [%1], 16;" :: "r"(dst), "l"(src));
}
#define CP_COMMIT() asm volatile("cp.async.commit_group;" ::: "memory")
#define CP_WAIT(n)  asm volatile("cp.async.wait_group %0;" :: "n"(n) : "memory")

#define LDSM4(r0, r1, r2, r3, addr) \
    asm volatile("ldmatrix.sync.aligned.m8n8.x4.shared.b16 {%0,%1,%2,%3}, [%4];" \
        : "=r"(r0), "=r"(r1), "=r"(r2), "=r"(r3) : "r"(addr))

__device__ __forceinline__ void mma_f16(float* c, const uint32_t* a, const uint32_t* b) {
    asm volatile(
        "mma.sync.aligned.m16n8k16.row.col.f32.f16.f16.f32 "
        "{%0,%1,%2,%3}, {%4,%5,%6,%7}, {%8,%9}, {%0,%1,%2,%3};"
        : "+f"(c[0]), "+f"(c[1]), "+f"(c[2]), "+f"(c[3])
        : "r"(a[0]), "r"(a[1]), "r"(a[2]), "r"(a[3]), "r"(b[0]), "r"(b[1]));
}

__device__ __forceinline__ float sig_(float x) {
    x = fminf(fmaxf(x, -30.f), 30.f);
    return __fdividef(1.f, 1.f + __expf(-x));
}
__device__ __forceinline__ float tanh_(float x) {
    x = fminf(fmaxf(x, -15.f), 15.f);
    float e = __expf(2.f * x);
    return __fdividef(e - 1.f, e + 1.f);
}

// ---------------- precompute: fp16 round of A (concat) and W^T ----------------
__global__ __launch_bounds__(256) void split_a_kernel(
    const float* __restrict__ hid, const float* __restrict__ inp)
{
    int i4 = blockIdx.x * 256 + threadIdx.x;   // float4 index over [4096][512]
    int row = i4 >> 9;
    int c4  = i4 & 511;
    const float4 v = (c4 < 256)
        ? *(const float4*)&hid[(size_t)row * 1024 + c4 * 4]
        : *(const float4*)&inp[(size_t)row * 1024 + (c4 - 256) * 4];
    __half h[4];
    h[0] = __float2half_rn(v.x);
    h[1] = __float2half_rn(v.y);
    h[2] = __float2half_rn(v.z);
    h[3] = __float2half_rn(v.w);
    *(uint2*)&g_Ah[(size_t)row * KDIM + c4 * 4] = *(uint2*)h;
}

__global__ __launch_bounds__(256) void split_b_kernel(
    const float* __restrict__ Wf, const float* __restrict__ Wi,
    const float* __restrict__ Wc, const float* __restrict__ Wo)
{
    __shared__ float tile[32][33];
    const int g = blockIdx.z;
    const float* W = (g == 0) ? Wf : (g == 1) ? Wi : (g == 2) ? Wc : Wo;
    const int n0 = blockIdx.x * 32;
    const int k0 = blockIdx.y * 32;
    const int tx = threadIdx.x & 31;
    const int ty = threadIdx.x >> 5;   // 0..7
    #pragma unroll
    for (int j = 0; j < 4; j++)
        tile[ty + 8 * j][tx] = W[(size_t)(k0 + ty + 8 * j) * UNITS + n0 + tx];
    __syncthreads();
    const int n_l = threadIdx.x >> 3;        // 0..31
    const int kq  = (threadIdx.x & 7) * 4;   // 0..28
    __half h[4];
    #pragma unroll
    for (int j = 0; j < 4; j++)
        h[j] = __float2half_rn(tile[kq + j][n_l]);
    size_t o = ((size_t)g * UNITS + n0 + n_l) * KDIM + k0 + kq;
    *(uint2*)&g_Bh[o] = *(uint2*)h;
}

// ---------------- fused GEMM + register epilogue ----------------
__global__ __launch_bounds__(256, 2) void gemm_kernel(
    const float* __restrict__ cell,
    const float* __restrict__ bfp, const float* __restrict__ bip,
    const float* __restrict__ bcp, const float* __restrict__ bop,
    float* __restrict__ out_h, float* __restrict__ out_c)
{
    extern __shared__ char smem[];
    const uint32_t sb = smem_u32(smem);
    const int tid  = threadIdx.x;
    const int wid  = tid >> 5;
    const int lane = tid & 31;
    const int warp_m = wid & 1;    // 64 rows
    const int warp_n = wid >> 1;   // 0..3 -> 8 units each, all 4 gates
    const int m0 = blockIdx.y * BM;
    const int n0 = blockIdx.x * BNU;

    // loader mapping: per array 1024 x 16B chunks; 4 per thread per array
    // chunk idx = tid + i*256; row = idx>>3 (0..127), c = idx&7 (16B group)
    auto issue_stage = [&](int s) {
        const int k0 = s * BK;
        const uint32_t base = sb + (s & 1) * STAGE_B;
        #pragma unroll
        for (int i = 0; i < 4; i++) {
            const int idx = tid + i * 256;
            const int row = idx >> 3;
            const int c   = idx & 7;
            // A tile
            cp16(base + OFF_AH + row * ROW_B + c * 16,
                 &g_Ah[(size_t)(m0 + row) * KDIM + k0 + c * 8]);
            // B tile: smem row = gate*32 + local_n
            const size_t gr = (size_t)(row >> 5) * UNITS + n0 + (row & 31);
            cp16(base + OFF_BH + row * ROW_B + c * 16,
                 &g_Bh[gr * KDIM + k0 + c * 8]);
        }
        CP_COMMIT();
    };

    // ldmatrix lane addressing (byte offsets within tile)
    const uint32_t a_off = (uint32_t)((warp_m * 64 + (lane & 15)) * ROW_B + (lane >> 4) * 16);
    // B: matrices = [gate 2p, k0-7], [gate 2p, k8-15], [gate 2p+1, k0-7], [gate 2p+1, k8-15]
    const uint32_t b_off = (uint32_t)((((lane >> 4) & 1) * 32 + warp_n * 8 + (lane & 7)) * ROW_B
                                      + ((lane >> 3) & 1) * 16);

    float acc[4][4][4];   // [mt rows][gate][q]
    #pragma unroll
    for (int i = 0; i < 4; i++)
        #pragma unroll
        for (int j = 0; j < 4; j++)
            #pragma unroll
            for (int q = 0; q < 4; q++) acc[i][j][q] = 0.f;

    issue_stage(0);

    #pragma unroll 1
    for (int s = 0; s < NSTAGE; s++) {
        if (s + 1 < NSTAGE) { issue_stage(s + 1); CP_WAIT(1); }
        else                { CP_WAIT(0); }
        __syncthreads();

        const uint32_t base = sb + (s & 1) * STAGE_B;
        #pragma unroll
        for (int ksub = 0; ksub < 4; ksub++) {
            const uint32_t kb = ksub * 32;
            uint32_t aH[4][4], bH[4][2];
            #pragma unroll
            for (int mt = 0; mt < 4; mt++) {
                const uint32_t ra = base + a_off + mt * 16 * ROW_B + kb;
                LDSM4(aH[mt][0], aH[mt][1], aH[mt][2], aH[mt][3], ra + OFF_AH);
            }
            #pragma unroll
            for (int p = 0; p < 2; p++) {
                const uint32_t rb = base + b_off + p * 64 * ROW_B + kb;
                LDSM4(bH[2*p][0], bH[2*p][1], bH[2*p+1][0], bH[2*p+1][1], rb + OFF_BH);
            }
            #pragma unroll
            for (int mt = 0; mt < 4; mt++)
                #pragma unroll
                for (int g = 0; g < 4; g++)
                    mma_f16(acc[mt][g], aH[mt], bH[g]);
        }
        __syncthreads();
    }

    // ---- register-direct epilogue
    const int fr = lane >> 2;
    const int fc = (lane & 3) * 2;
    const int ucol = n0 + warp_n * 8 + fc;
    const float2 Bf = *(const float2*)&bfp[ucol];
    const float2 Bi = *(const float2*)&bip[ucol];
    const float2 Bc = *(const float2*)&bcp[ucol];
    const float2 Bo = *(const float2*)&bop[ucol];

    #pragma unroll
    for (int mt = 0; mt < 4; mt++) {
        #pragma unroll
        for (int q = 0; q < 2; q++) {
            const int row = m0 + warp_m * 64 + mt * 16 + fr + q * 8;
            const size_t go = (size_t)row * UNITS + ucol;
            const float2 cp = *(const float2*)&cell[go];
            const float pf0 = acc[mt][0][2*q],   pf1 = acc[mt][0][2*q+1];
            const float pi0 = acc[mt][1][2*q],   pi1 = acc[mt][1][2*q+1];
            const float pc0 = acc[mt][2][2*q],   pc1 = acc[mt][2][2*q+1];
            const float po0 = acc[mt][3][2*q],   po1 = acc[mt][3][2*q+1];

            float2 nh, nc;
            {
                const float f  = sig_(pf0 + Bf.x), ig = sig_(pi0 + Bi.x);
                const float cc = tanh_(pc0 + Bc.x), o = sig_(po0 + Bo.x);
                nc.x = f * cp.x + ig * cc; nh.x = o * tanh_(nc.x);
            }
            {
                const float f  = sig_(pf1 + Bf.y), ig = sig_(pi1 + Bi.y);
                const float cc = tanh_(pc1 + Bc.y), o = sig_(po1 + Bo.y);
                nc.y = f * cp.y + ig * cc; nh.y = o * tanh_(nc.y);
            }
            *(float2*)&out_h[go] = nh;
            *(float2*)&out_c[go] = nc;
        }
    }
}

// ---------------- host launch ----------------
extern "C" void kernel_launch(void* const* d_in, const int* in_sizes, int n_in,
                              void* d_out, int out_size) {
    const float* inp  = (const float*)d_in[0];
    const float* hid  = (const float*)d_in[1];
    const float* cell = (const float*)d_in[2];
    const float* Wf   = (const float*)d_in[3];
    const float* bf   = (const float*)d_in[4];
    const float* Wi   = (const float*)d_in[5];
    const float* bi   = (const float*)d_in[6];
    const float* Wc   = (const float*)d_in[7];
    const float* bc   = (const float*)d_in[8];
    const float* Wo   = (const float*)d_in[9];
    const float* bo   = (const float*)d_in[10];

    float* out_h = (float*)d_out;
    float* out_c = out_h + (size_t)BATCH * UNITS;

    cudaFuncSetAttribute(gemm_kernel,
                         cudaFuncAttributeMaxDynamicSharedMemorySize, SMEM_TOTAL);

    split_a_kernel<<<(BATCH * (KDIM / 4)) / 256, 256>>>(hid, inp);
    split_b_kernel<<<dim3(UNITS / 32, KDIM / 32, 4), 256>>>(Wf, Wi, Wc, Wo);
    gemm_kernel<<<dim3(UNITS / BNU, BATCH / BM), 256, SMEM_TOTAL>>>(
        cell, bf, bi, bc, bo, out_h, out_c);
}